// round 16
// baseline (speedup 1.0000x reference)
#include <cuda_runtime.h>
#include <cuda_fp16.h>
#include <math.h>
#include <stdint.h>

#define L_ 8
#define H_ 16
#define T_ 2048
#define C_ 1024
#define OUT_ 1024
#define B_ 4
#define DH_ 64
#define FF_ 4096
#define M_ (B_*T_)   // 8192 rows

#define CC_ (C_*C_)                   // 1048576
#define WPL_ (12*CC_)                 // weights per layer (halves)
#define WOFF_WO  (3*CC_)
#define WOFF_W1  (4*CC_)
#define WOFF_W2  (8*CC_)
#define WHEAD_OFF ((size_t)L_*WPL_)   // 100663296
#define WTOT (WHEAD_OFF + CC_)        // 101711872

// q pre-scale: 0.125 (1/sqrt(DH)) * log2(e) -> softmax in base-2 domain
#define QSCALE 0.1803368801111204f

// ---------------- scratch (static device globals) ----------------
__device__ float g_x[M_*C_];
__device__ __align__(16) __half g_hh[M_*C_],  g_hl[M_*C_];
__device__ __align__(16) __half g_qkvh[3*M_*C_];
__device__ __align__(16) __half g_yh[M_*C_];
__device__ __align__(16) __half g_uh[(size_t)M_*FF_];
__device__ __align__(16) __half g_wh[WTOT],   g_wl[WTOT];
__device__ float g_bqkv[L_*3*C_];

// ================= helpers =================
__device__ __forceinline__ uint32_t smem_u32(const void* p) {
    uint32_t a;
    asm("{ .reg .u64 t; cvta.to.shared.u64 t, %1; cvt.u32.u64 %0, t; }" : "=r"(a) : "l"(p));
    return a;
}
__device__ __forceinline__ void mma16816(float* c, const uint32_t* a, uint32_t b0, uint32_t b1) {
    asm volatile(
        "mma.sync.aligned.m16n8k16.row.col.f32.f16.f16.f32 "
        "{%0,%1,%2,%3}, {%4,%5,%6,%7}, {%8,%9}, {%0,%1,%2,%3};"
        : "+f"(c[0]), "+f"(c[1]), "+f"(c[2]), "+f"(c[3])
        : "r"(a[0]), "r"(a[1]), "r"(a[2]), "r"(a[3]), "r"(b0), "r"(b1));
}
__device__ __forceinline__ void ldsm4(uint32_t* r, uint32_t addr) {
    asm volatile("ldmatrix.sync.aligned.m8n8.x4.shared.b16 {%0,%1,%2,%3}, [%4];"
                 : "=r"(r[0]), "=r"(r[1]), "=r"(r[2]), "=r"(r[3]) : "r"(addr));
}
__device__ __forceinline__ void ldsm4t(uint32_t* r, uint32_t addr) {
    asm volatile("ldmatrix.sync.aligned.m8n8.x4.trans.shared.b16 {%0,%1,%2,%3}, [%4];"
                 : "=r"(r[0]), "=r"(r[1]), "=r"(r[2]), "=r"(r[3]) : "r"(addr));
}
#define CP_ASYNC16(dst, src) \
    asm volatile("cp.async.cg.shared.global [%0], [%1], 16;" :: "r"(dst), "l"(src))
#define CP_COMMIT asm volatile("cp.async.commit_group;" ::: "memory")
#define CP_WAIT(n) asm volatile("cp.async.wait_group %0;" :: "n"(n) : "memory")

__device__ __forceinline__ float fex2(float x) {
    float y;
    asm("ex2.approx.f32 %0, %1;" : "=f"(y) : "f"(x));
    return y;
}
// two exps in one MUFU op: pack (a,b) to half2, ex2.approx.f16x2
__device__ __forceinline__ uint32_t ex2_h2(float a, float b) {
    __half2 hv = __floats2half2_rn(a, b);
    uint32_t r;
    asm("ex2.approx.f16x2 %0, %1;" : "=r"(r) : "r"(*(uint32_t*)&hv));
    return r;
}
__device__ __forceinline__ void split2(float x, float y, uint32_t& h, uint32_t& l) {
    __half2 hh = __floats2half2_rn(x, y);
    float2 hf = __half22float2(hh);
    __half2 ll = __floats2half2_rn(x - hf.x, y - hf.y);
    h = *(uint32_t*)&hh;
    l = *(uint32_t*)&ll;
}
__device__ __forceinline__ uint32_t pack_h2(float x, float y) {
    __half2 hh = __floats2half2_rn(x, y);
    return *(uint32_t*)&hh;
}
__device__ __forceinline__ float gelu_exact(float v) {
    return 0.5f * v * (1.0f + erff(v * 0.70710678118654752f));
}

// ================= fused weight conversion (single launch) =================
__global__ void __launch_bounds__(256) conv_all(
    const float* __restrict__ Wq, const float* __restrict__ Wk,
    const float* __restrict__ Wv, const float* __restrict__ Wo,
    const float* __restrict__ W1, const float* __restrict__ W2,
    const float* __restrict__ Whd,
    __half* __restrict__ dh, __half* __restrict__ dl)
{
    const size_t i = ((size_t)blockIdx.x * 256 + threadIdx.x) * 8;
    const float* src;
    if (i >= WHEAD_OFF) {
        src = Whd + (i - WHEAD_OFF);
    } else {
        const int l = (int)(i / WPL_);
        const size_t r = i % WPL_;
        if      (r <   (size_t)CC_)   src = Wq + (size_t)l*CC_   + r;
        else if (r < 2*(size_t)CC_)   src = Wk + (size_t)l*CC_   + (r -   CC_);
        else if (r < 3*(size_t)CC_)   src = Wv + (size_t)l*CC_   + (r - 2*CC_);
        else if (r < 4*(size_t)CC_)   src = Wo + (size_t)l*CC_   + (r - 3*CC_);
        else if (r < 8*(size_t)CC_)   src = W1 + (size_t)l*4*CC_ + (r - 4*CC_);
        else                          src = W2 + (size_t)l*4*CC_ + (r - 8*CC_);
    }
    float4 a = *(const float4*)(src), b = *(const float4*)(src + 4);
    uint32_t h[4], l4[4];
    split2(a.x, a.y, h[0], l4[0]); split2(a.z, a.w, h[1], l4[1]);
    split2(b.x, b.y, h[2], l4[2]); split2(b.z, b.w, h[3], l4[3]);
    *(uint4*)(dh + i) = make_uint4(h[0], h[1], h[2], h[3]);
    if (i >= WHEAD_OFF)
        *(uint4*)(dl + i) = make_uint4(l4[0], l4[1], l4[2], l4[3]);
}
__global__ void __launch_bounds__(256) packqkvb(
    const float* __restrict__ bq, const float* __restrict__ bk,
    const float* __restrict__ bv, float* __restrict__ dst)
{
    int idx = blockIdx.x * 256 + threadIdx.x;      // L_*3072
    int l = idx / 3072, c = idx % 3072;
    float v = (c < 1024) ? bq[l*1024 + c] : (c < 2048) ? bk[l*1024 + c - 1024]
                                                        : bv[l*1024 + c - 2048];
    dst[idx] = v;
}

// ================= x = seq + pos =================
__global__ void __launch_bounds__(256) addpos_kernel(
    const float* __restrict__ seq, const float* __restrict__ pos, float* __restrict__ x)
{
    int i = blockIdx.x * 256 + threadIdx.x;
    float4 s = ((const float4*)seq)[i];
    float4 p = ((const float4*)pos)[i & (T_*C_/4 - 1)];
    s.x += p.x; s.y += p.y; s.z += p.z; s.w += p.w;
    ((float4*)x)[i] = s;
}

// ================= LayerNorm -> fp16 hi (+ optional lo) =================
__global__ void __launch_bounds__(256) ln_split(
    const float* __restrict__ x, const float* __restrict__ w,
    const float* __restrict__ b, __half* __restrict__ outh, __half* __restrict__ outl)
{
    const int row = blockIdx.x;
    const int t = threadIdx.x;
    const float4 v = *(const float4*)(x + (size_t)row * C_ + t * 4);
    float s  = v.x + v.y + v.z + v.w;
    float sq = v.x*v.x + v.y*v.y + v.z*v.z + v.w*v.w;
    #pragma unroll
    for (int off = 16; off; off >>= 1) {
        s  += __shfl_xor_sync(0xffffffffu, s,  off);
        sq += __shfl_xor_sync(0xffffffffu, sq, off);
    }
    __shared__ float rs_[8], rq_[8];
    if ((t & 31) == 0) { rs_[t >> 5] = s; rq_[t >> 5] = sq; }
    __syncthreads();
    s = 0.f; sq = 0.f;
    #pragma unroll
    for (int i = 0; i < 8; i++) { s += rs_[i]; sq += rq_[i]; }
    const float mu   = s * (1.0f / 1024.0f);
    const float var  = sq * (1.0f / 1024.0f) - mu * mu;
    const float rstd = rsqrtf(var + 1e-5f);
    const float4 wv = *(const float4*)(w + t * 4);
    const float4 bv = *(const float4*)(b + t * 4);
    float ox = (v.x - mu) * rstd * wv.x + bv.x;
    float oy = (v.y - mu) * rstd * wv.y + bv.y;
    float oz = (v.z - mu) * rstd * wv.z + bv.z;
    float ow = (v.w - mu) * rstd * wv.w + bv.w;
    uint32_t h0, l0, h1, l1;
    split2(ox, oy, h0, l0);
    split2(oz, ow, h1, l1);
    *(uint2*)(outh + (size_t)row * C_ + t * 4) = make_uint2(h0, h1);
    if (outl) *(uint2*)(outl + (size_t)row * C_ + t * 4) = make_uint2(l0, l1);
}

// ================= 1-pass fp16 GEMM, 256x128 block, 64x64 warp tile =================
#define GSTG2 49152u
#define GEMM_SMEM2 (3*49152)

template <int EPI>
__global__ void __launch_bounds__(256, 1) gemm_h2(
    const __half* __restrict__ Ah,
    const __half* __restrict__ Wh,
    const float* __restrict__ bias, const float* __restrict__ resid,
    float* __restrict__ outf, __half* __restrict__ outh,
    int N, int K)
{
    extern __shared__ char sm[];
    const uint32_t sb = smem_u32(sm);
    const int t = threadIdx.x, w = t >> 5, lane = t & 31;
    const int bm = blockIdx.y, bn = blockIdx.x;
    const int wm = w & 3, wn = w >> 2;

    const int crow = t >> 1, chalf = t & 1;
    const __half* agh = Ah + (size_t)(bm*256 + crow) * K + chalf*32;
    const __half* bgh = Wh + (size_t)(bn*128 + crow) * K + chalf*32;
    uint32_t dsto[4];
    #pragma unroll
    for (int i = 0; i < 4; i++) {
        int c16 = chalf*4 + i;
        dsto[i] = (uint32_t)(crow*128 + ((c16 ^ (crow & 7)) << 4));
    }
    auto load_stage = [&](int c, int slot) {
        const uint32_t s0 = sb + (uint32_t)slot * GSTG2;
        const __half* a0 = agh + c*64;
        const __half* b0 = bgh + c*64;
        #pragma unroll
        for (int i = 0; i < 4; i++) CP_ASYNC16(s0 + dsto[i],           a0 + i*8);
        #pragma unroll
        for (int i = 0; i < 4; i++) CP_ASYNC16(s0 + 16384u + dsto[i],  a0 + (size_t)128*K + i*8);
        #pragma unroll
        for (int i = 0; i < 4; i++) CP_ASYNC16(s0 + 32768u + dsto[i],  b0 + i*8);
    };

    const int ra = lane & 15, ca = lane >> 4;
    const int rb = (lane & 7) + ((lane >> 4) << 3), cb = (lane >> 3) & 1;
    const int xr = lane & 7;
    const uint32_t aro = (uint32_t)((wm*64 + ra) * 128);
    const uint32_t bro = (uint32_t)((wn*64 + rb) * 128);

    float acc[4][8][4];
    #pragma unroll
    for (int i = 0; i < 4; i++)
        #pragma unroll
        for (int j = 0; j < 8; j++)
            #pragma unroll
            for (int r = 0; r < 4; r++) acc[i][j][r] = 0.f;

    load_stage(0, 0); CP_COMMIT;
    load_stage(1, 1); CP_COMMIT;

    const int NC = K >> 6;
    int slot = 0;
    for (int c = 0; c < NC; c++) {
        CP_WAIT(1);
        __syncthreads();
        if (c + 2 < NC) {
            int ns = slot + 2; if (ns >= 3) ns -= 3;
            load_stage(c + 2, ns);
        }
        CP_COMMIT;
        const uint32_t st = sb + (uint32_t)slot * GSTG2;
        #pragma unroll
        for (int ks = 0; ks < 4; ks++) {
            const uint32_t kca = (uint32_t)(((ks*2 + ca) ^ xr) << 4);
            const uint32_t kcb = (uint32_t)(((ks*2 + cb) ^ xr) << 4);
            uint32_t ah[4][4], bh[4][4];
            #pragma unroll
            for (int mt = 0; mt < 4; mt++)
                ldsm4(ah[mt], st + aro + mt*2048u + kca);
            #pragma unroll
            for (int nq = 0; nq < 4; nq++)
                ldsm4(bh[nq], st + 32768u + bro + nq*2048u + kcb);
            #pragma unroll
            for (int mt = 0; mt < 4; mt++)
                #pragma unroll
                for (int nt = 0; nt < 8; nt++) {
                    const int nq = nt >> 1, s2 = (nt & 1) * 2;
                    mma16816(acc[mt][nt], ah[mt], bh[nq][s2], bh[nq][s2+1]);
                }
        }
        slot = (slot + 1 == 3) ? 0 : slot + 1;
    }

    // ---- epilogue ----
    const int grbase = bm*256 + wm*64;
    const int gcbase = bn*128 + wn*64;
    #pragma unroll
    for (int mt = 0; mt < 4; mt++) {
        const int r0 = grbase + mt*16 + (lane >> 2);
        #pragma unroll
        for (int nt = 0; nt < 8; nt++) {
            const int gc = gcbase + nt*8 + (lane & 3)*2;
            float2 v0 = make_float2(acc[mt][nt][0], acc[mt][nt][1]);
            float2 v1 = make_float2(acc[mt][nt][2], acc[mt][nt][3]);
            {
                float2 bb = *(const float2*)(bias + gc);
                v0.x += bb.x; v0.y += bb.y; v1.x += bb.x; v1.y += bb.y;
            }
            if (EPI == 1) {
                const int third = gc >> 10, lc = gc & 1023;
                __half* oh = outh + (size_t)third * ((size_t)M_ * C_);
                if (third == 0) {
                    v0.x *= QSCALE; v0.y *= QSCALE; v1.x *= QSCALE; v1.y *= QSCALE;
                }
                *(uint32_t*)(oh + (size_t)r0 * 1024 + lc)     = pack_h2(v0.x, v0.y);
                *(uint32_t*)(oh + (size_t)(r0+8) * 1024 + lc) = pack_h2(v1.x, v1.y);
            } else if (EPI == 2) {
                v0.x = gelu_exact(v0.x); v0.y = gelu_exact(v0.y);
                v1.x = gelu_exact(v1.x); v1.y = gelu_exact(v1.y);
                *(uint32_t*)(outh + (size_t)r0 * N + gc)     = pack_h2(v0.x, v0.y);
                *(uint32_t*)(outh + (size_t)(r0+8) * N + gc) = pack_h2(v1.x, v1.y);
            } else {  // EPI == 3
                float2 ra2 = *(const float2*)(resid + (size_t)r0 * N + gc);
                float2 rb2 = *(const float2*)(resid + (size_t)(r0+8) * N + gc);
                v0.x += ra2.x; v0.y += ra2.y; v1.x += rb2.x; v1.y += rb2.y;
                *(float2*)(outf + (size_t)r0 * N + gc) = v0;
                *(float2*)(outf + (size_t)(r0+8) * N + gc) = v1;
            }
        }
    }
}

// ================= head GEMM: 3-pass, 128x128 block =================
#define GSTG3 65536u
#define GEMM_SMEM3 (3*65536)

__global__ void __launch_bounds__(256, 1) gemm_head(
    const __half* __restrict__ Ah, const __half* __restrict__ Al,
    const __half* __restrict__ Wh, const __half* __restrict__ Wl,
    float* __restrict__ outf, int N, int K)
{
    extern __shared__ char sm[];
    const uint32_t sb = smem_u32(sm);
    const int t = threadIdx.x, w = t >> 5, lane = t & 31;
    const int bm = blockIdx.y, bn = blockIdx.x;
    const int wm = w & 3, wn = w >> 2;

    const int crow = t >> 1, chalf = t & 1;
    const __half* agh = Ah + (size_t)(bm*128 + crow) * K + chalf*32;
    const __half* agl = Al + (size_t)(bm*128 + crow) * K + chalf*32;
    const __half* bgh = Wh + (size_t)(bn*128 + crow) * K + chalf*32;
    const __half* bgl = Wl + (size_t)(bn*128 + crow) * K + chalf*32;
    uint32_t dsto[4];
    #pragma unroll
    for (int i = 0; i < 4; i++) {
        int c16 = chalf*4 + i;
        dsto[i] = (uint32_t)(crow*128 + ((c16 ^ (crow & 7)) << 4));
    }
    auto load_stage = [&](int c, int slot) {
        const uint32_t s0 = sb + (uint32_t)slot * GSTG3;
        #pragma unroll
        for (int i = 0; i < 4; i++) CP_ASYNC16(s0 + dsto[i],          agh + c*64 + i*8);
        #pragma unroll
        for (int i = 0; i < 4; i++) CP_ASYNC16(s0 + 16384u + dsto[i], agl + c*64 + i*8);
        #pragma unroll
        for (int i = 0; i < 4; i++) CP_ASYNC16(s0 + 32768u + dsto[i], bgh + c*64 + i*8);
        #pragma unroll
        for (int i = 0; i < 4; i++) CP_ASYNC16(s0 + 49152u + dsto[i], bgl + c*64 + i*8);
    };

    const int ra = lane & 15, ca = lane >> 4;
    const int rb = (lane & 7) + ((lane >> 4) << 3), cb = (lane >> 3) & 1;
    const int xr = lane & 7;
    const uint32_t aro = (uint32_t)((wm*32 + ra) * 128);
    const uint32_t bro = (uint32_t)((wn*64 + rb) * 128);

    float acc[2][8][4];
    #pragma unroll
    for (int i = 0; i < 2; i++)
        #pragma unroll
        for (int j = 0; j < 8; j++)
            #pragma unroll
            for (int r = 0; r < 4; r++) acc[i][j][r] = 0.f;

    load_stage(0, 0); CP_COMMIT;
    load_stage(1, 1); CP_COMMIT;

    const int NC = K >> 6;
    int slot = 0;
    for (int c = 0; c < NC; c++) {
        CP_WAIT(1);
        __syncthreads();
        if (c + 2 < NC) {
            int ns = slot + 2; if (ns >= 3) ns -= 3;
            load_stage(c + 2, ns);
        }
        CP_COMMIT;
        const uint32_t st = sb + (uint32_t)slot * GSTG3;
        #pragma unroll
        for (int ks = 0; ks < 4; ks++) {
            const uint32_t kca = (uint32_t)(((ks*2 + ca) ^ xr) << 4);
            const uint32_t kcb = (uint32_t)(((ks*2 + cb) ^ xr) << 4);
            uint32_t ah[2][4], al4[2][4], bh[4][4], bl4[4][4];
            #pragma unroll
            for (int mt = 0; mt < 2; mt++) {
                ldsm4(ah[mt],  st + aro + mt*2048u + kca);
                ldsm4(al4[mt], st + 16384u + aro + mt*2048u + kca);
            }
            #pragma unroll
            for (int nq = 0; nq < 4; nq++) {
                ldsm4(bh[nq],  st + 32768u + bro + nq*2048u + kcb);
                ldsm4(bl4[nq], st + 49152u + bro + nq*2048u + kcb);
            }
            #pragma unroll
            for (int mt = 0; mt < 2; mt++)
                #pragma unroll
                for (int nt = 0; nt < 8; nt++) {
                    const int nq = nt >> 1, s2 = (nt & 1) * 2;
                    mma16816(acc[mt][nt], ah[mt], bh[nq][s2], bh[nq][s2+1]);
                }
            #pragma unroll
            for (int mt = 0; mt < 2; mt++)
                #pragma unroll
                for (int nt = 0; nt < 8; nt++) {
                    const int nq = nt >> 1, s2 = (nt & 1) * 2;
                    mma16816(acc[mt][nt], ah[mt], bl4[nq][s2], bl4[nq][s2+1]);
                }
            #pragma unroll
            for (int mt = 0; mt < 2; mt++)
                #pragma unroll
                for (int nt = 0; nt < 8; nt++) {
                    const int nq = nt >> 1, s2 = (nt & 1) * 2;
                    mma16816(acc[mt][nt], al4[mt], bh[nq][s2], bh[nq][s2+1]);
                }
        }
        slot = (slot + 1 == 3) ? 0 : slot + 1;
    }

    const int grbase = bm*128 + wm*32;
    const int gcbase = bn*128 + wn*64;
    #pragma unroll
    for (int mt = 0; mt < 2; mt++) {
        const int r0 = grbase + mt*16 + (lane >> 2);
        #pragma unroll
        for (int nt = 0; nt < 8; nt++) {
            const int gc = gcbase + nt*8 + (lane & 3)*2;
            *(float2*)(outf + (size_t)r0 * N + gc) =
                make_float2(acc[mt][nt][0], acc[mt][nt][1]);
            *(float2*)(outf + (size_t)(r0+8) * N + gc) =
                make_float2(acc[mt][nt][2], acc[mt][nt][3]);
        }
    }
}

// ================= flash attention: 1-pass fp16, Q tile 128, KV tile 128 =================
// 8 warps, each warp 16 Q rows. 16 KV tiles of 128 tokens -> half the softmax segments.
// smem: Qh[128x64]@0 (16KB), then 3 stages of 32KB: Kh[128x64]@0, Vh[128x64]@16K.
#define ASTG 32768
#define AQSZ 16384
#define ATT_SMEM (AQSZ + 3*ASTG)

__global__ void __launch_bounds__(256, 1) attn_h(
    const __half* __restrict__ qkvh, __half* __restrict__ yh)
{
    extern __shared__ char sm[];
    const uint32_t sb = smem_u32(sm);
    const int t = threadIdx.x, w = t >> 5, lane = t & 31;
    const int bhx = blockIdx.y, b = bhx >> 4, h = bhx & 15;
    const int q0 = blockIdx.x * 128;
    const size_t MC = (size_t)M_ * C_;
    const int NT = T_ / 128;   // 16 tiles

    const __half* qgh = qkvh + (size_t)(b*T_ + q0) * C_ + h*64;
    const __half* kgh = qkvh + MC   + (size_t)(b*T_) * C_ + h*64;
    const __half* vgh = qkvh + 2*MC + (size_t)(b*T_) * C_ + h*64;

    // Q loads: row = t>>1, half-row = t&1 (4 chunks each, chunk = 8 halves)
    {
        const int qr = t >> 1, qc = t & 1;
        const __half* qrow = qgh + (size_t)qr * C_;
        #pragma unroll
        for (int i = 0; i < 4; i++) {
            const int c16 = qc*4 + i;
            const uint32_t d = (uint32_t)(qr*128 + ((c16 ^ (qr & 7)) << 4));
            CP_ASYNC16(sb + d, qrow + c16*8);
        }
    }
    CP_COMMIT;

    // KV stage loader: 128 rows each of K and V; row = t>>1, 4 chunks per row each
    const int kr = t >> 1, kc = t & 1;
    auto load_kv = [&](int kt, int slot) {
        const uint32_t s0 = sb + AQSZ + (uint32_t)slot * ASTG;
        const size_t rowoff = (size_t)(kt*128 + kr) * C_;
        #pragma unroll
        for (int i = 0; i < 4; i++) {
            const int c16 = kc*4 + i;
            const uint32_t d = (uint32_t)(kr*128 + ((c16 ^ (kr & 7)) << 4));
            CP_ASYNC16(s0 + d,          kgh + rowoff + c16*8);
            CP_ASYNC16(s0 + 16384u + d, vgh + rowoff + c16*8);
        }
    };
    load_kv(0, 0); CP_COMMIT;
    load_kv(1, 1); CP_COMMIT;

    const int ra = lane & 15, ca = lane >> 4;
    const int rb = (lane & 7) + ((lane >> 4) << 3), cb = (lane >> 3) & 1;
    const int rv = (lane & 7) + (((lane >> 3) & 1) << 3), cv = lane >> 4;
    const int xr = lane & 7;

    CP_WAIT(2);           // Q landed
    __syncthreads();
    uint32_t qh4[4][4];
    {
        const uint32_t qro = (uint32_t)((w*16 + ra) * 128);
        #pragma unroll
        for (int ks = 0; ks < 4; ks++) {
            const uint32_t off = qro + (uint32_t)(((ks*2 + ca) ^ xr) << 4);
            ldsm4(qh4[ks], sb + off);
        }
    }

    float o_[8][4];
    #pragma unroll
    for (int i = 0; i < 8; i++)
        #pragma unroll
        for (int j = 0; j < 4; j++) o_[i][j] = 0.f;
    float m_a = -1e30f, m_b = -1e30f, l_a = 0.f, l_b = 0.f;

    int slot = 0;
    for (int kt = 0; kt < NT; kt++) {
        CP_WAIT(1);
        __syncthreads();
        if (kt + 2 < NT) {
            int ns = slot + 2; if (ns >= 3) ns -= 3;
            load_kv(kt + 2, ns);
        }
        CP_COMMIT;
        const uint32_t st = sb + AQSZ + (uint32_t)slot * ASTG;

        // ---- S = qh·kh (1-pass), warp tile 16x128 ----
        float sc[16][4];
        #pragma unroll
        for (int i = 0; i < 16; i++)
            #pragma unroll
            for (int j = 0; j < 4; j++) sc[i][j] = 0.f;
        #pragma unroll
        for (int ks = 0; ks < 4; ks++) {
            uint32_t kh4[8][4];
            #pragma unroll
            for (int nq = 0; nq < 8; nq++) {
                const uint32_t off = (uint32_t)((nq*16 + rb) * 128)
                                   + (uint32_t)(((ks*2 + cb) ^ xr) << 4);
                ldsm4(kh4[nq], st + off);
            }
            #pragma unroll
            for (int nt = 0; nt < 16; nt++) {
                const int nq = nt >> 1, s2 = (nt & 1) * 2;
                mma16816(sc[nt], qh4[ks], kh4[nq][s2], kh4[nq][s2+1]);
            }
        }

        // ---- online softmax (base-2, fp16x2 exp -> P packed) ----
        uint32_t pc[16][2];
        {
            float mxa = -1e30f, mxb = -1e30f;
            #pragma unroll
            for (int nt = 0; nt < 16; nt++) {
                mxa = fmaxf(mxa, fmaxf(sc[nt][0], sc[nt][1]));
                mxb = fmaxf(mxb, fmaxf(sc[nt][2], sc[nt][3]));
            }
            mxa = fmaxf(mxa, __shfl_xor_sync(0xffffffffu, mxa, 1));
            mxa = fmaxf(mxa, __shfl_xor_sync(0xffffffffu, mxa, 2));
            mxb = fmaxf(mxb, __shfl_xor_sync(0xffffffffu, mxb, 1));
            mxb = fmaxf(mxb, __shfl_xor_sync(0xffffffffu, mxb, 2));
            const float nma = fmaxf(m_a, mxa), nmb = fmaxf(m_b, mxb);
            const float cfa = fex2(m_a - nma), cfb = fex2(m_b - nmb);
            m_a = nma; m_b = nmb;
            float rsa = 0.f, rsb = 0.f;
            #pragma unroll
            for (int nt = 0; nt < 16; nt++) {
                const uint32_t e01 = ex2_h2(sc[nt][0] - nma, sc[nt][1] - nma);
                const uint32_t e23 = ex2_h2(sc[nt][2] - nmb, sc[nt][3] - nmb);
                pc[nt][0] = e01;
                pc[nt][1] = e23;
                float2 f01 = __half22float2(*(const __half2*)&e01);
                float2 f23 = __half22float2(*(const __half2*)&e23);
                rsa += f01.x + f01.y;
                rsb += f23.x + f23.y;
            }
            rsa += __shfl_xor_sync(0xffffffffu, rsa, 1);
            rsa += __shfl_xor_sync(0xffffffffu, rsa, 2);
            rsb += __shfl_xor_sync(0xffffffffu, rsb, 1);
            rsb += __shfl_xor_sync(0xffffffffu, rsb, 2);
            l_a = l_a * cfa + rsa;
            l_b = l_b * cfb + rsb;
            #pragma unroll
            for (int dt = 0; dt < 8; dt++) {
                o_[dt][0] *= cfa; o_[dt][1] *= cfa;
                o_[dt][2] *= cfb; o_[dt][3] *= cfb;
            }
        }

        // ---- O += ph·vh (1-pass), 8 token-steps of 16 ----
        #pragma unroll
        for (int ks = 0; ks < 8; ks++) {
            uint32_t ph[4];
            ph[0] = pc[2*ks][0];
            ph[1] = pc[2*ks][1];
            ph[2] = pc[2*ks+1][0];
            ph[3] = pc[2*ks+1][1];
            uint32_t vh4[4][4];
            #pragma unroll
            for (int nq = 0; nq < 4; nq++) {
                const uint32_t off = (uint32_t)((ks*16 + rv) * 128)
                                   + (uint32_t)(((nq*2 + cv) ^ xr) << 4);
                ldsm4t(vh4[nq], st + 16384u + off);
            }
            #pragma unroll
            for (int dt = 0; dt < 8; dt++) {
                const int nq = dt >> 1, s2 = (dt & 1) * 2;
                mma16816(o_[dt], ph, vh4[nq][s2], vh4[nq][s2+1]);
            }
        }
        slot = (slot + 1 == 3) ? 0 : slot + 1;
    }

    // ---- write y (fp16 hi only) ----
    const float ia = 1.f / l_a, ib = 1.f / l_b;
    const int r0 = q0 + w*16 + (lane >> 2);
    __half* ybh = yh + (size_t)(b*T_ + r0) * C_ + h*64;
    #pragma unroll
    for (int dt = 0; dt < 8; dt++) {
        const int gc = dt*8 + (lane & 3)*2;
        *(uint32_t*)(ybh + gc)                = pack_h2(o_[dt][0]*ia, o_[dt][1]*ia);
        *(uint32_t*)(ybh + (size_t)8*C_ + gc) = pack_h2(o_[dt][2]*ib, o_[dt][3]*ib);
    }
}

// ================= orchestration =================
extern "C" void kernel_launch(void* const* d_in, const int* in_sizes, int n_in,
                              void* d_out, int out_size)
{
    const float* seq  = (const float*)d_in[0];
    const float* pos  = (const float*)d_in[1];
    const float* Wq   = (const float*)d_in[2];
    const float* bq   = (const float*)d_in[3];
    const float* Wk   = (const float*)d_in[4];
    const float* bk   = (const float*)d_in[5];
    const float* Wv   = (const float*)d_in[6];
    const float* bv   = (const float*)d_in[7];
    const float* Wo   = (const float*)d_in[8];
    const float* bo   = (const float*)d_in[9];
    const float* ln1w = (const float*)d_in[10];
    const float* ln1b = (const float*)d_in[11];
    const float* ln2w = (const float*)d_in[12];
    const float* ln2b = (const float*)d_in[13];
    const float* W1   = (const float*)d_in[14];
    const float* b1   = (const float*)d_in[15];
    const float* W2   = (const float*)d_in[16];
    const float* b2   = (const float*)d_in[17];
    const float* lnfw = (const float*)d_in[18];
    const float* lnfb = (const float*)d_in[19];
    const float* Wh   = (const float*)d_in[20];
    float* out = (float*)d_out;

    float *px, *pbqkv;
    __half *phh, *phl, *pqkvh, *pyh, *puh, *pwh, *pwl;
    cudaGetSymbolAddress((void**)&px, g_x);
    cudaGetSymbolAddress((void**)&phh, g_hh);
    cudaGetSymbolAddress((void**)&phl, g_hl);
    cudaGetSymbolAddress((void**)&pqkvh, g_qkvh);
    cudaGetSymbolAddress((void**)&pyh, g_yh);
    cudaGetSymbolAddress((void**)&puh, g_uh);
    cudaGetSymbolAddress((void**)&pwh, g_wh);
    cudaGetSymbolAddress((void**)&pwl, g_wl);
    cudaGetSymbolAddress((void**)&pbqkv, g_bqkv);

    cudaFuncSetAttribute(attn_h, cudaFuncAttributeMaxDynamicSharedMemorySize, ATT_SMEM);
    cudaFuncSetAttribute((gemm_h2<1>), cudaFuncAttributeMaxDynamicSharedMemorySize, GEMM_SMEM2);
    cudaFuncSetAttribute((gemm_h2<2>), cudaFuncAttributeMaxDynamicSharedMemorySize, GEMM_SMEM2);
    cudaFuncSetAttribute((gemm_h2<3>), cudaFuncAttributeMaxDynamicSharedMemorySize, GEMM_SMEM2);
    cudaFuncSetAttribute(gemm_head, cudaFuncAttributeMaxDynamicSharedMemorySize, GEMM_SMEM3);

    // ---- weight conversion: ONE launch ----
    conv_all<<<(int)(WTOT / 2048), 256>>>(Wq, Wk, Wv, Wo, W1, W2, Wh, pwh, pwl);
    packqkvb<<<L_*3*C_/256, 256>>>(bq, bk, bv, pbqkv);
    addpos_kernel<<<M_ * C_ / 4 / 256, 256>>>(seq, pos, px);

    dim3 gQKV(3*C_ / 128, M_ / 256);   // (24, 32)
    dim3 gC(C_ / 128, M_ / 256);       // (8, 32)
    dim3 gF(FF_ / 128, M_ / 256);      // (32, 32)
    dim3 gA(T_ / 128, B_ * H_);        // (16, 64)
    dim3 gHead(OUT_ / 128, M_ / 128);  // (8, 64)

    for (int l = 0; l < L_; l++) {
        const size_t wl = (size_t)l * WPL_;
        ln_split<<<M_, 256>>>(px, ln1w + l*C_, ln1b + l*C_, phh, nullptr);
        gemm_h2<1><<<gQKV, 256, GEMM_SMEM2>>>(phh, pwh + wl,
            pbqkv + l*3*C_, nullptr, nullptr, pqkvh, 3*C_, C_);
        attn_h<<<gA, 256, ATT_SMEM>>>(pqkvh, pyh);
        gemm_h2<3><<<gC, 256, GEMM_SMEM2>>>(pyh, pwh + wl + WOFF_WO,
            bo + l*C_, px, px, nullptr, C_, C_);
        ln_split<<<M_, 256>>>(px, ln2w + l*C_, ln2b + l*C_, phh, nullptr);
        gemm_h2<2><<<gF, 256, GEMM_SMEM2>>>(phh, pwh + wl + WOFF_W1,
            b1 + l*FF_, nullptr, nullptr, puh, FF_, C_);
        gemm_h2<3><<<gC, 256, GEMM_SMEM2>>>(puh, pwh + wl + WOFF_W2,
            b2 + l*C_, px, px, nullptr, C_, FF_);
    }

    // final LN needs lo for the 3-pass head GEMM
    ln_split<<<M_, 256>>>(px, lnfw, lnfb, phh, phl);
    gemm_head<<<gHead, 256, GEMM_SMEM3>>>(phh, phl, pwh + WHEAD_OFF, pwl + WHEAD_OFF,
        out, OUT_, C_);
}